// round 17
// baseline (speedup 1.0000x reference)
#include <cuda_runtime.h>
#include <math.h>
#include <stdint.h>

#define T 2048
#define C 1024
#define H 16
#define HD 64
#define TOPK 64
#define HEDGE_BAND 5e-6f
#define HEDGE_SIGMA 1.1e-6f

// libdevice precise intrinsics (immune to fast-math)
extern "C" __device__ float __nv_powf(float, float);
extern "C" __device__ float __nv_cosf(float);
extern "C" __device__ float __nv_sinf(float);
extern "C" __device__ float __nv_expf(float);
extern "C" __device__ float __nv_erff(float);

// ---- device scratch ----
__device__ float g_qkv[(size_t)T * 3 * C];
__device__ float g_gate[(size_t)T * C];
__device__ float g_Q[(size_t)H * T * HD];
__device__ float g_K[(size_t)H * T * HD];
__device__ float g_V[(size_t)H * T * HD];
__device__ float g_S[(size_t)H * T * T];
__device__ float g_yg[(size_t)T * C];

// ---------------------------------------------------------------
// Double-buffered 128x128 SGEMM body (unchanged from R15/R16).
// ---------------------------------------------------------------
__device__ __forceinline__ void gemm128_db(
    const float* __restrict__ A, const float* __restrict__ B,
    float* __restrict__ Cout, int N, int K, int act, int bm, int bn,
    float (&As)[2][16][132], float (&Bs)[2][16][132])
{
    int t = threadIdx.x;
    int lr = t >> 2;
    int lk = (t & 3) << 2;
    int rm = (t >> 4) << 3;
    int rn = (t & 15) << 3;
    float acc[8][8];
#pragma unroll
    for (int i = 0; i < 8; i++)
#pragma unroll
        for (int j = 0; j < 8; j++) acc[i][j] = 0.f;

    const float* Ap0 = A + (size_t)(bm + lr) * K + lk;
    const float* Ap1 = Ap0 + (size_t)64 * K;
    const float* Bp0 = B + (size_t)(bn + lr) * K + lk;
    const float* Bp1 = Bp0 + (size_t)64 * K;

    float4 ra0 = *(const float4*)(Ap0);
    float4 ra1 = *(const float4*)(Ap1);
    float4 rb0 = *(const float4*)(Bp0);
    float4 rb1 = *(const float4*)(Bp1);

    int buf = 0;
    for (int k0 = 0; k0 < K; k0 += 16) {
        As[buf][lk + 0][lr] = ra0.x; As[buf][lk + 1][lr] = ra0.y;
        As[buf][lk + 2][lr] = ra0.z; As[buf][lk + 3][lr] = ra0.w;
        As[buf][lk + 0][lr + 64] = ra1.x; As[buf][lk + 1][lr + 64] = ra1.y;
        As[buf][lk + 2][lr + 64] = ra1.z; As[buf][lk + 3][lr + 64] = ra1.w;
        Bs[buf][lk + 0][lr] = rb0.x; Bs[buf][lk + 1][lr] = rb0.y;
        Bs[buf][lk + 2][lr] = rb0.z; Bs[buf][lk + 3][lr] = rb0.w;
        Bs[buf][lk + 0][lr + 64] = rb1.x; Bs[buf][lk + 1][lr + 64] = rb1.y;
        Bs[buf][lk + 2][lr + 64] = rb1.z; Bs[buf][lk + 3][lr + 64] = rb1.w;
        __syncthreads();
        if (k0 + 16 < K) {
            ra0 = *(const float4*)(Ap0 + k0 + 16);
            ra1 = *(const float4*)(Ap1 + k0 + 16);
            rb0 = *(const float4*)(Bp0 + k0 + 16);
            rb1 = *(const float4*)(Bp1 + k0 + 16);
        }
#pragma unroll
        for (int kk = 0; kk < 16; kk++) {
            float a[8], b[8];
#pragma unroll
            for (int i = 0; i < 8; i++) a[i] = As[buf][kk][rm + i];
#pragma unroll
            for (int j = 0; j < 8; j++) b[j] = Bs[buf][kk][rn + j];
#pragma unroll
            for (int i = 0; i < 8; i++)
#pragma unroll
                for (int j = 0; j < 8; j++) acc[i][j] += a[i] * b[j];
        }
        buf ^= 1;
    }
#pragma unroll
    for (int i = 0; i < 8; i++) {
        size_t ro = (size_t)(bm + rm + i) * N + bn + rn;
#pragma unroll
        for (int j = 0; j < 8; j++) {
            float v = acc[i][j];
            if (act) {
                float s = __frcp_rn(1.f + __nv_expf(-v));
                v = v * s;
            }
            Cout[ro + j] = v;
        }
    }
}

__global__ __launch_bounds__(256, 2)
void sgemm_tn128(const float* __restrict__ A, const float* __restrict__ B,
                 float* __restrict__ Cout, int N, int K, int act)
{
    __shared__ float As[2][16][132];
    __shared__ float Bs[2][16][132];
    gemm128_db(A, B, Cout, N, K, act, blockIdx.y * 128, blockIdx.x * 128, As, Bs);
}

__global__ __launch_bounds__(256, 2)
void sgemm_qkvgate(const float* __restrict__ x,
                   const float* __restrict__ w_attn,
                   const float* __restrict__ w_gate,
                   float* __restrict__ qkv, float* __restrict__ gate)
{
    __shared__ float As[2][16][132];
    __shared__ float Bs[2][16][132];
    int bx = blockIdx.x;
    if (bx < 24)
        gemm128_db(x, w_attn, qkv, 3 * C, C, 0, blockIdx.y * 128, bx * 128, As, Bs);
    else
        gemm128_db(x, w_gate, gate, C, C, 1, blockIdx.y * 128, (bx - 24) * 128, As, Bs);
}

// ---------------------------------------------------------------
// Scores: K=HD=64 smem-resident (unchanged).
// ---------------------------------------------------------------
__global__ __launch_bounds__(256, 2)
void qk_score_k64(const float* __restrict__ Qg, const float* __restrict__ Kg,
                  float* __restrict__ S)
{
    int bkx = blockIdx.x, bqy = blockIdx.y, h = blockIdx.z;
    if (bkx > bqy) return;
    __shared__ float As[64][132];
    __shared__ float Bs[64][132];
    const float* A = Qg + (size_t)h * T * HD;
    const float* B = Kg + (size_t)h * T * HD;
    float* Sh = S + (size_t)h * T * T;
    int t = threadIdx.x;
    int bm = bqy * 128, bn = bkx * 128;
    int lr = t >> 2;
    int kc = (t & 3) << 4;
    int rm = (t >> 4) << 3, rn = (t & 15) << 3;

#pragma unroll
    for (int i = 0; i < 4; i++) {
        float4 a0 = *(const float4*)(A + (size_t)(bm + lr) * HD + kc + 4 * i);
        float4 a1 = *(const float4*)(A + (size_t)(bm + lr + 64) * HD + kc + 4 * i);
        float4 b0 = *(const float4*)(B + (size_t)(bn + lr) * HD + kc + 4 * i);
        float4 b1 = *(const float4*)(B + (size_t)(bn + lr + 64) * HD + kc + 4 * i);
        int k = kc + 4 * i;
        As[k + 0][lr] = a0.x; As[k + 1][lr] = a0.y; As[k + 2][lr] = a0.z; As[k + 3][lr] = a0.w;
        As[k + 0][lr + 64] = a1.x; As[k + 1][lr + 64] = a1.y; As[k + 2][lr + 64] = a1.z; As[k + 3][lr + 64] = a1.w;
        Bs[k + 0][lr] = b0.x; Bs[k + 1][lr] = b0.y; Bs[k + 2][lr] = b0.z; Bs[k + 3][lr] = b0.w;
        Bs[k + 0][lr + 64] = b1.x; Bs[k + 1][lr + 64] = b1.y; Bs[k + 2][lr + 64] = b1.z; Bs[k + 3][lr + 64] = b1.w;
    }
    __syncthreads();

    float acc[8][8];
#pragma unroll
    for (int i = 0; i < 8; i++)
#pragma unroll
        for (int j = 0; j < 8; j++) acc[i][j] = 0.f;

#pragma unroll
    for (int kk = 0; kk < 64; kk++) {
        float a[8], b[8];
#pragma unroll
        for (int i = 0; i < 8; i++) a[i] = As[kk][rm + i];
#pragma unroll
        for (int j = 0; j < 8; j++) b[j] = Bs[kk][rn + j];
#pragma unroll
        for (int i = 0; i < 8; i++)
#pragma unroll
            for (int j = 0; j < 8; j++) acc[i][j] += a[i] * b[j];
    }
#pragma unroll
    for (int i = 0; i < 8; i++) {
        size_t ro = (size_t)(bm + rm + i) * T + bn + rn;
#pragma unroll
        for (int j = 0; j < 8; j++)
            Sh[ro + j] = acc[i][j] * 0.125f;
    }
}

// ---------------------------------------------------------------
// RoPE (unchanged from R16).
// ---------------------------------------------------------------
__global__ __launch_bounds__(512)
void rope_permute(const float* __restrict__ qkv,
                  float* __restrict__ Q, float* __restrict__ K,
                  float* __restrict__ V)
{
    __shared__ float s_cs[32], s_sn[32];
    int t = blockIdx.x;
    int tid = threadIdx.x;
    int d = tid & 31, h = tid >> 5;
    if (tid < 32) {
        float e  = (float)(2 * tid) * (1.f / 64.f);
        float p  = __nv_powf(10000.0f, e);
        float inv = __frcp_rn(p);
        float fr = __fmul_rn((float)t, inv);
        s_cs[tid] = __nv_cosf(fr);
        s_sn[tid] = __nv_sinf(fr);
    }
    __syncthreads();
    const float* base = qkv + (size_t)t * (3 * C) + h * HD;
    float q1 = base[d],         q2 = base[d + 32];
    float k1 = base[C + d],     k2 = base[C + d + 32];
    float v1 = base[2 * C + d], v2 = base[2 * C + d + 32];
    float cs = s_cs[d], sn = s_sn[d];
    size_t o = ((size_t)h * T + t) * HD;
    Q[o + d]      = __fadd_rn(__fmul_rn(q1, cs), -__fmul_rn(q2, sn));
    Q[o + d + 32] = __fadd_rn(__fmul_rn(q2, cs),  __fmul_rn(q1, sn));
    K[o + d]      = __fadd_rn(__fmul_rn(k1, cs), -__fmul_rn(k2, sn));
    K[o + d + 32] = __fadd_rn(__fmul_rn(k2, cs),  __fmul_rn(k1, sn));
    V[o + d]      = v1;
    V[o + d + 32] = v2;
}

// monotone float<->uint order-preserving maps
__device__ __forceinline__ unsigned f2u(float f) {
    unsigned u = __float_as_uint(f);
    return (u & 0x80000000u) ? ~u : (u | 0x80000000u);
}
__device__ __forceinline__ float u2f(unsigned u) {
    return (u & 0x80000000u) ? __uint_as_float(u & 0x7fffffffu)
                             : __uint_as_float(~u);
}

// warp-aggregated histogram add: one atomic per distinct bucket per warp
__device__ __forceinline__ void hist_add(unsigned* hist, unsigned bucket, bool active) {
    unsigned act = __ballot_sync(0xffffffffu, active);
    if (active) {
        unsigned mm = __match_any_sync(act, bucket);
        int leader = __ffs(mm) - 1;
        if ((int)(threadIdx.x & 31) == leader)
            atomicAdd(&hist[bucket], (unsigned)__popc(mm));
    }
}

// ---------------------------------------------------------------
// select_av v4: identical selection results; serialization removed.
//  - warp-aggregated histogram atomics (match_any)
//  - ballot-aggregated compactions
//  - shuffle-based reductions (2 barriers instead of 16)
// ---------------------------------------------------------------
__global__ void select_av(const float* __restrict__ S, const float* __restrict__ V,
                          const float* __restrict__ gate,
                          const float* __restrict__ span_params,
                          float* __restrict__ yg)
{
    __shared__ float s_sc[T];
    __shared__ float s_w[T];
    __shared__ int   s_k[T];
    __shared__ unsigned s_hist[256];
    __shared__ float s_red[256];
    __shared__ float s_rA[8], s_rB[8];
    __shared__ unsigned long long s_pk[8];
    __shared__ int s_cnt, s_kneed, s_ncand, s_cEQ, s_k64i, s_cEQ65;
    __shared__ unsigned s_prefix;
    __shared__ float s_e64, s_m64, s_bc0, s_bc1;

    int q = blockIdx.x, h = blockIdx.y, tid = threadIdx.x;
    int lane = tid & 31, wid = tid >> 5;
    int len = q + 1;
    bool over = (len > TOPK);
    const float* Srow = S + ((size_t)h * T + q) * T;

    s_hist[tid] = 0;
    if (tid == 0) {
        s_kneed = TOPK; s_prefix = 0u; s_cnt = 0; s_ncand = 0;
        s_cEQ = 0; s_k64i = -1; s_cEQ65 = 0;
    }
    __syncthreads();

    // ---- Pass A: load + local max + aggregated top-byte histogram ----
    float lmax = -3.402823466e38f;
    int iters = (len + 255) >> 8;
    for (int it = 0; it < iters; it++) {
        int k = it * 256 + tid;
        bool active = (k < len);
        float v = 0.f;
        unsigned bucket = 0;
        if (active) {
            v = Srow[k];
            s_sc[k] = v;
            lmax = fmaxf(lmax, v);
            bucket = f2u(v) >> 24;
        }
        if (over) hist_add(s_hist, bucket, active);
    }
    // rowmax: warp shuffle + cross-warp
#pragma unroll
    for (int o = 16; o > 0; o >>= 1)
        lmax = fmaxf(lmax, __shfl_xor_sync(0xffffffffu, lmax, o));
    if (lane == 0) s_rA[wid] = lmax;
    __syncthreads();
    if (tid == 0) {
        float m = s_rA[0];
#pragma unroll
        for (int i = 1; i < 8; i++) m = fmaxf(m, s_rA[i]);
        s_bc0 = m;
    }
    __syncthreads();
    float rowmax = s_bc0;

    unsigned thresh_u = 0u;
    if (over) {
        // pass 3 bucket select (warp 0 suffix scan)
        if (tid < 32) {
            int kneed = s_kneed;
            unsigned hl[8];
            unsigned lanesum = 0;
            int base = tid << 3;
#pragma unroll
            for (int i = 0; i < 8; i++) { hl[i] = s_hist[base + i]; lanesum += hl[i]; }
            unsigned run = lanesum;
#pragma unroll
            for (int o = 1; o < 32; o <<= 1) {
                unsigned v = __shfl_down_sync(0xffffffffu, run, o);
                if (tid + o < 32) run += v;
            }
            unsigned Sabove = run - lanesum;
#pragma unroll
            for (int i = 7; i >= 0; i--) {
                if (Sabove < (unsigned)kneed && Sabove + hl[i] >= (unsigned)kneed) {
                    s_prefix = (unsigned)(base + i) << 24;
                    s_kneed = kneed - (int)Sabove;
                }
                Sabove += hl[i];
            }
        }
        __syncthreads();

        // compact candidates (ballot-aggregated)
        unsigned top = s_prefix >> 24;
        for (int it = 0; it < iters; it++) {
            int k = it * 256 + tid;
            bool pred = (k < len) && ((f2u(s_sc[k]) >> 24) == top);
            unsigned act = __ballot_sync(0xffffffffu, pred);
            if (pred) {
                int leader = __ffs(act) - 1;
                unsigned rank = __popc(act & ((1u << lane) - 1));
                int base;
                if (lane == leader) base = atomicAdd(&s_ncand, __popc(act));
                base = __shfl_sync(act, base, leader);
                s_k[base + rank] = k;
            }
        }
        __syncthreads();
        int ncand = s_ncand;
        int citers = (ncand + 255) >> 8;

        // passes 2..0 over candidates (aggregated histogram)
        for (int pass = 2; pass >= 0; pass--) {
            int shift = pass * 8;
            s_hist[tid] = 0;
            __syncthreads();
            unsigned pfx = s_prefix;
            for (int it = 0; it < citers; it++) {
                int i = it * 256 + tid;
                bool active = (i < ncand);
                unsigned u = 0, bucket = 0;
                bool match = false;
                if (active) {
                    u = f2u(s_sc[s_k[i]]);
                    match = (((u ^ pfx) >> (shift + 8)) == 0u);
                    bucket = (u >> shift) & 255u;
                }
                hist_add(s_hist, bucket, active && match);
            }
            __syncthreads();
            if (tid < 32) {
                int kneed = s_kneed;
                unsigned pfx0 = s_prefix;
                unsigned hl[8];
                unsigned lanesum = 0;
                int base = tid << 3;
#pragma unroll
                for (int i = 0; i < 8; i++) { hl[i] = s_hist[base + i]; lanesum += hl[i]; }
                unsigned run = lanesum;
#pragma unroll
                for (int o = 1; o < 32; o <<= 1) {
                    unsigned v = __shfl_down_sync(0xffffffffu, run, o);
                    if (tid + o < 32) run += v;
                }
                unsigned Sabove = run - lanesum;
#pragma unroll
                for (int i = 7; i >= 0; i--) {
                    if (Sabove < (unsigned)kneed && Sabove + hl[i] >= (unsigned)kneed) {
                        s_prefix = pfx0 | ((unsigned)(base + i) << shift);
                        s_kneed = kneed - (int)Sabove;
                    }
                    Sabove += hl[i];
                }
            }
            __syncthreads();
        }
        thresh_u = s_prefix;
    }
    __syncthreads();
    if (tid == 0) s_cnt = 0;
    __syncthreads();

    // ---- fused keep pass + u65 argmax (ballot-aggregated compaction) ----
    float span = span_params[h];
    span = 2048.f * fminf(fmaxf(span, 0.f), 1.f);
    float e_sum = 0.f, em_sum = 0.f;
    unsigned long long lpack = 0ull;
    for (int it = 0; it < iters; it++) {
        int k = it * 256 + tid;
        bool inb = (k < len);
        float v = 0.f; unsigned u = 0;
        bool keep = false;
        float w = 0.f;
        if (inb) {
            v = s_sc[k];
            u = f2u(v);
            keep = !over || (u >= thresh_u);
            if (keep) {
                float e = __nv_expf(v - rowmax);
                float dist = (float)(q - k);
                float m = fminf(fmaxf((32.f + span - dist) * (1.f / 32.f), 0.f), 1.f);
                e_sum += e;
                w = e * m;
                em_sum += w;
                if (over && u == thresh_u) {
                    atomicAdd(&s_cEQ, 1);
                    s_k64i = k; s_e64 = e; s_m64 = m;
                }
            } else {
                unsigned long long pk = ((unsigned long long)u << 32) | (unsigned)k;
                if (pk > lpack) lpack = pk;
            }
        }
        bool pred = inb && keep && (w > 0.f);
        unsigned act = __ballot_sync(0xffffffffu, pred);
        if (pred) {
            int leader = __ffs(act) - 1;
            unsigned rank = __popc(act & ((1u << lane) - 1));
            int base;
            if (lane == leader) base = atomicAdd(&s_cnt, __popc(act));
            base = __shfl_sync(act, base, leader);
            s_k[base + rank] = k;
            s_w[base + rank] = w;
        }
    }
    // combined reduction: e_sum, em_sum (shuffle), pack (max)
#pragma unroll
    for (int o = 16; o > 0; o >>= 1) {
        e_sum  += __shfl_xor_sync(0xffffffffu, e_sum, o);
        em_sum += __shfl_xor_sync(0xffffffffu, em_sum, o);
        unsigned long long op = __shfl_xor_sync(0xffffffffu, lpack, o);
        if (op > lpack) lpack = op;
    }
    if (lane == 0) { s_rA[wid] = e_sum; s_rB[wid] = em_sum; s_pk[wid] = lpack; }
    __syncthreads();
    if (tid == 0) {
        float ea = 0.f, ema = 0.f;
        unsigned long long pk = 0ull;
#pragma unroll
        for (int i = 0; i < 8; i++) {
            ea += s_rA[i]; ema += s_rB[i];
            if (s_pk[i] > pk) pk = s_pk[i];
        }
        s_bc0 = ea; s_bc1 = ema; s_pk[0] = pk;
    }
    __syncthreads();
    float EA = s_bc0, EMA = s_bc1;
    unsigned long long pk0 = s_pk[0];
    unsigned u65 = (unsigned)(pk0 >> 32);
    int k65i = (int)(pk0 & 0xffffffffull);
    float denomA = EMA + 1e-8f * EA;
    float invA = (denomA > 0.f) ? __frcp_rn(denomA) : 0.f;
    int cnt = s_cnt;

    // ---- hedge (rare) ----
    bool amb = false;
    float pA = 1.f, invB = 0.f;
    float e64 = 0.f, m64 = 0.f, e65 = 0.f, m65 = 0.f;
    int k64i = -1;
    if (over && s_cEQ == 1 && pk0 != 0ull) {
        float f64 = u2f(thresh_u), f65 = u2f(u65);
        float gap = fmaxf(f64 - f65, 0.f);
        if (gap < HEDGE_BAND) {
            for (int k = tid; k < len; k += 256)
                if (f2u(s_sc[k]) == u65) atomicAdd(&s_cEQ65, 1);
            __syncthreads();
            if (s_cEQ65 == 1) {
                amb = true;
                pA = 0.5f * (1.f + __nv_erff(gap * (0.70710678f / HEDGE_SIGMA)));
                e64 = s_e64; m64 = s_m64; k64i = s_k64i;
                e65 = __nv_expf(u2f(u65) - rowmax);
                float dist65 = (float)(q - k65i);
                m65 = fminf(fmaxf((32.f + span - dist65) * (1.f / 32.f), 0.f), 1.f);
                float EB  = EA - e64 + e65;
                float EMB = EMA - e64 * m64 + e65 * m65;
                float denomB = EMB + 1e-8f * EB;
                invB = (denomB > 0.f) ? __frcp_rn(denomB) : 0.f;
            }
        }
    }
    __syncthreads();

    // ---- sparse AV ----
    int d = tid & 63, part = tid >> 6;
    const float* Vh = V + (size_t)h * T * HD;
    float acc = 0.f;
    for (int i = part; i < cnt; i += 4)
        acc += s_w[i] * Vh[(size_t)s_k[i] * HD + d];
    s_red[tid] = acc;
    __syncthreads();
    if (tid < 64) {
        float YA = s_red[tid] + s_red[tid + 64] + s_red[tid + 128] + s_red[tid + 192];
        float y;
        if (amb) {
            float c64 = e64 * m64 * Vh[(size_t)k64i * HD + d];
            float c65 = e65 * m65 * Vh[(size_t)k65i * HD + d];
            float YB = YA - c64 + c65;
            y = pA * (YA * invA) + (1.f - pA) * (YB * invB);
        } else {
            y = YA * invA;
        }
        size_t o = (size_t)q * C + h * HD + d;
        yg[o] = y * gate[o];
    }
}

// ---------------------------------------------------------------
extern "C" void kernel_launch(void* const* d_in, const int* in_sizes, int n_in,
                              void* d_out, int out_size)
{
    const float* x       = (const float*)d_in[0];
    const float* w_attn  = (const float*)d_in[1];
    const float* w_proj  = (const float*)d_in[2];
    const float* w_gate  = (const float*)d_in[3];
    const float* span    = (const float*)d_in[4];
    float* out = (float*)d_out;
    (void)in_sizes; (void)n_in; (void)out_size;

    float *qkv, *gatep, *Q, *K, *V, *S, *yg;
    cudaGetSymbolAddress((void**)&qkv,   g_qkv);
    cudaGetSymbolAddress((void**)&gatep, g_gate);
    cudaGetSymbolAddress((void**)&Q,     g_Q);
    cudaGetSymbolAddress((void**)&K,     g_K);
    cudaGetSymbolAddress((void**)&V,     g_V);
    cudaGetSymbolAddress((void**)&S,     g_S);
    cudaGetSymbolAddress((void**)&yg,    g_yg);

    dim3 blk(256);
    sgemm_qkvgate<<<dim3(32, T / 128), blk>>>(x, w_attn, w_gate, qkv, gatep);
    rope_permute<<<T, 512>>>(qkv, Q, K, V);
    qk_score_k64<<<dim3(T / 128, T / 128, H), blk>>>(Q, K, S);
    select_av<<<dim3(T, H), blk>>>(S, V, gatep, span, yg);
    sgemm_tn128<<<dim3(C / 128, T / 128), blk>>>(yg, w_proj, out, C, C, 0);
}